// round 1
// baseline (speedup 1.0000x reference)
#include <cuda_runtime.h>

#define CCH 96
#define KVOL 27
#define ROWS_PER_BLOCK 4

// Flag: 1 if neighbor_map is stored as int64, 0 if int32.
__device__ int g_idx_is64;

__global__ void detect_idx_dtype(const void* __restrict__ nmap,
                                 long long n_in_rows, int elem_count) {
    // Interpret the first few entries as int64. Genuine int64 indices are all
    // in [0, n_in_rows). If the buffer is really int32, each int64 read packs
    // two random indices (lo + hi*2^32) and is virtually guaranteed to fall
    // outside that range within a few samples.
    const long long* p = (const long long*)nmap;
    int n_check = 64;
    int avail = elem_count / 2;           // safe int64 reads even if int32
    if (avail < n_check) n_check = avail;
    int ok64 = 1;
    for (int i = 0; i < n_check; ++i) {
        long long v = p[i];
        if (v < 0 || v >= n_in_rows) { ok64 = 0; break; }
    }
    g_idx_is64 = ok64;
}

__global__ __launch_bounds__(CCH * ROWS_PER_BLOCK)
void sparse_maxpool_kernel(const float* __restrict__ in_feat,
                           const void* __restrict__ nmap,
                           float* __restrict__ out,
                           int n_out) {
    int row = blockIdx.x * ROWS_PER_BLOCK + threadIdx.y;
    if (row >= n_out) return;
    int c = threadIdx.x;                              // channel 0..95

    const float* feat_c = in_feat + c;
    float m = -__int_as_float(0x7f800000) * 1.0f;     // -inf
    m = -__builtin_huge_valf();

    if (g_idx_is64) {
        const long long* nm = (const long long*)nmap + (long long)row * KVOL;
        #pragma unroll 9
        for (int k = 0; k < KVOL; ++k) {
            long long idx = nm[k];                    // warp-uniform broadcast
            m = fmaxf(m, __ldg(feat_c + idx * CCH));
        }
    } else {
        const int* nm = (const int*)nmap + row * KVOL;
        #pragma unroll 9
        for (int k = 0; k < KVOL; ++k) {
            long long idx = (long long)nm[k];
            m = fmaxf(m, __ldg(feat_c + idx * CCH));
        }
    }

    out[(long long)row * CCH + c] = m;
}

extern "C" void kernel_launch(void* const* d_in, const int* in_sizes, int n_in,
                              void* d_out, int out_size) {
    const float* in_feat = (const float*)d_in[0];
    const void*  nmap    = (const void*)d_in[1];
    float*       out     = (float*)d_out;

    int nmap_elems       = in_sizes[1];          // N_OUT * KVOL
    int n_out            = nmap_elems / KVOL;    // 100000
    long long n_in_rows  = (long long)in_sizes[0] / CCH;  // 400000

    detect_idx_dtype<<<1, 1>>>(nmap, n_in_rows, nmap_elems);

    dim3 block(CCH, ROWS_PER_BLOCK);
    int grid = (n_out + ROWS_PER_BLOCK - 1) / ROWS_PER_BLOCK;
    sparse_maxpool_kernel<<<grid, block>>>(in_feat, nmap, out, n_out);
}

// round 2
// speedup vs baseline: 1.3511x; 1.3511x over previous
#include <cuda_runtime.h>
#include <math_constants.h>

#define KVOL 27
#define C4   24                 // 96 channels = 24 float4
#define ROWS_PER_BLOCK 16       // 24*16 = 384 threads

// Flag: 1 if neighbor_map is stored as int64, 0 if int32.
__device__ int g_idx_is64;

__global__ void detect_idx_dtype(const void* __restrict__ nmap,
                                 long long n_in_rows, int elem_count) {
    const long long* p = (const long long*)nmap;
    int n_check = 64;
    int avail = elem_count / 2;
    if (avail < n_check) n_check = avail;
    int ok64 = 1;
    for (int i = 0; i < n_check; ++i) {
        long long v = p[i];
        if (v < 0 || v >= n_in_rows) { ok64 = 0; break; }
    }
    g_idx_is64 = ok64;
}

__device__ __forceinline__ void vmax(float4& m, const float4 v) {
    m.x = fmaxf(m.x, v.x);
    m.y = fmaxf(m.y, v.y);
    m.z = fmaxf(m.z, v.z);
    m.w = fmaxf(m.w, v.w);
}

template <typename IDX>
__device__ __forceinline__ void pool_row(const float4* __restrict__ feat,
                                         const IDX* __restrict__ nm,
                                         float4* __restrict__ outp) {
    float4 m = make_float4(-CUDART_INF_F, -CUDART_INF_F, -CUDART_INF_F, -CUDART_INF_F);
    #pragma unroll
    for (int kb = 0; kb < KVOL; kb += 9) {
        long long idx[9];
        #pragma unroll
        for (int j = 0; j < 9; ++j)
            idx[j] = (long long)__ldcs(&nm[kb + j]);   // streaming: don't pollute L2
        float4 v[9];
        #pragma unroll
        for (int j = 0; j < 9; ++j)
            v[j] = __ldg(feat + idx[j] * C4);          // 9 x 16B in flight
        #pragma unroll
        for (int j = 0; j < 9; ++j)
            vmax(m, v[j]);
    }
    __stcs(outp, m);                                   // streaming store
}

__global__ __launch_bounds__(C4 * ROWS_PER_BLOCK)
void sparse_maxpool_kernel(const float4* __restrict__ in_feat,
                           const void* __restrict__ nmap,
                           float4* __restrict__ out,
                           int n_out) {
    int row = blockIdx.x * ROWS_PER_BLOCK + threadIdx.y;
    if (row >= n_out) return;
    int c4 = threadIdx.x;                              // 0..23

    const float4* feat_c = in_feat + c4;
    float4* outp = out + (long long)row * C4 + c4;

    if (g_idx_is64) {
        const long long* nm = (const long long*)nmap + (long long)row * KVOL;
        pool_row(feat_c, nm, outp);
    } else {
        const int* nm = (const int*)nmap + (long long)row * KVOL;
        pool_row(feat_c, nm, outp);
    }
}

extern "C" void kernel_launch(void* const* d_in, const int* in_sizes, int n_in,
                              void* d_out, int out_size) {
    const float4* in_feat = (const float4*)d_in[0];
    const void*   nmap    = (const void*)d_in[1];
    float4*       out     = (float4*)d_out;

    int nmap_elems      = in_sizes[1];                    // N_OUT * KVOL
    int n_out           = nmap_elems / KVOL;              // 100000
    long long n_in_rows = (long long)in_sizes[0] / 96;    // 400000

    detect_idx_dtype<<<1, 1>>>(nmap, n_in_rows, nmap_elems);

    dim3 block(C4, ROWS_PER_BLOCK);
    int grid = (n_out + ROWS_PER_BLOCK - 1) / ROWS_PER_BLOCK;
    sparse_maxpool_kernel<<<grid, block>>>(in_feat, nmap, out, n_out);
}